// round 6
// baseline (speedup 1.0000x reference)
#include <cuda_runtime.h>
#include <cuda_bf16.h>
#include <cstdint>

// DispersiveLoss: loss = 0.5 * mean_{b,s,t!=s}[ LSE_s - sim_st ], sim = cos/0.1
// Per row: (S-1)*(log(sum_{t!=s} e^{sim-10}) + 10) - 10*sum_{t!=s} cos
// Symmetric pairs (i<=j); Ai resident in SMEM, Aj streamed in K-quarters.
// sm_103 (non-'a'): mma.sync bf16 + ldmatrix + cp.async.

namespace {
constexpr int BATCH = 8, SEQ = 2048, DIM = 512;
constexpr int NBLK = 16;
constexpr int NPAIR = NBLK * (NBLK + 1) / 2;   // 136
constexpr float L2E10 = 14.4269504088896341f;  // 10*log2(e)
constexpr int OFF_AI  = 0;                 // 128 rows x 1024B, swizzled
constexpr int OFF_J0  = 131072;            // quarter buf: 128 rows x 256B
constexpr int OFF_J1  = 163840;
constexpr int OFF_RED = 196608;            // 1536 floats
constexpr int SMEM_TOTAL = OFF_RED + 6144; // 202752
}

__device__ __nv_bfloat16 g_ln[(size_t)BATCH * SEQ * DIM];
__device__ float g_es[BATCH * NBLK * NBLK * 128];
__device__ float g_vs[BATCH * NBLK * NBLK * 128];
__device__ float g_partial[128];
__device__ unsigned int g_done;

__device__ __forceinline__ uint32_t smem_u32(const void* p) {
    uint32_t a;
    asm("{ .reg .u64 t; cvta.to.shared.u64 t, %1; cvt.u32.u64 %0, t; }" : "=r"(a) : "l"(p));
    return a;
}
#define CP_ASYNC16(sa, ga) \
    asm volatile("cp.async.cg.shared.global [%0], [%1], 16;" :: "r"(sa), "l"(ga))
#define CP_COMMIT() asm volatile("cp.async.commit_group;")
#define CP_WAITN(n) asm volatile("cp.async.wait_group %0;" :: "n"(n))
#define LDSM_X4(r0, r1, r2, r3, addr) \
    asm volatile("ldmatrix.sync.aligned.m8n8.x4.shared.b16 {%0,%1,%2,%3}, [%4];" \
                 : "=r"(r0), "=r"(r1), "=r"(r2), "=r"(r3) : "r"(addr))
#define LDSM_X4T(r0, r1, r2, r3, addr) \
    asm volatile("ldmatrix.sync.aligned.m8n8.x4.trans.shared.b16 {%0,%1,%2,%3}, [%4];" \
                 : "=r"(r0), "=r"(r1), "=r"(r2), "=r"(r3) : "r"(addr))
#define MMA16816(c, A0, A1, A2, A3, B0, B1) \
    asm volatile("mma.sync.aligned.m16n8k16.row.col.f32.bf16.bf16.f32 " \
                 "{%0,%1,%2,%3}, {%4,%5,%6,%7}, {%8,%9}, {%0,%1,%2,%3};" \
                 : "+f"((c)[0]), "+f"((c)[1]), "+f"((c)[2]), "+f"((c)[3]) \
                 : "r"(A0), "r"(A1), "r"(A2), "r"(A3), "r"(B0), "r"(B1))

// ---------------- kernel 1: L2-normalize rows -> bf16 (warp per row) ------
__global__ void __launch_bounds__(256) disp_norm(const float* __restrict__ x) {
    const int wid = threadIdx.x >> 5, lane = threadIdx.x & 31;
    const int row = blockIdx.x * 8 + wid;
    const float4* src = reinterpret_cast<const float4*>(x + (size_t)row * DIM);
    float4 v[4];
#pragma unroll
    for (int k = 0; k < 4; ++k) v[k] = src[lane + 32 * k];
    float ss = 0.f;
#pragma unroll
    for (int k = 0; k < 4; ++k)
        ss += v[k].x * v[k].x + v[k].y * v[k].y + v[k].z * v[k].z + v[k].w * v[k].w;
#pragma unroll
    for (int o = 16; o; o >>= 1) ss += __shfl_xor_sync(0xFFFFFFFFu, ss, o);
    const float inv = 1.0f / fmaxf(sqrtf(ss), 1e-8f);
    __nv_bfloat162* dst = reinterpret_cast<__nv_bfloat162*>(g_ln + (size_t)row * DIM);
#pragma unroll
    for (int k = 0; k < 4; ++k) {
        dst[(lane + 32 * k) * 2 + 0] = __floats2bfloat162_rn(v[k].x * inv, v[k].y * inv);
        dst[(lane + 32 * k) * 2 + 1] = __floats2bfloat162_rn(v[k].z * inv, v[k].w * inv);
    }
}

// ---------------- kernel 2: symmetric tile-pair GEMM + exp-sums ----------
__global__ void __launch_bounds__(256, 1) disp_main() {
    extern __shared__ char smem[];
    const uint32_t sb = smem_u32(smem);
    const int tid = threadIdx.x, wid = tid >> 5, lane = tid & 31;
    const int bx = blockIdx.x;
    const int b = bx / NPAIR;
    int p = bx - b * NPAIR;
    int i = 0;
    while (p >= NBLK - i) { p -= NBLK - i; ++i; }
    const int j = i + p;
    const bool diag = (i == j);

    const char* Ai = (const char*)(g_ln + ((size_t)b * SEQ + i * 128) * DIM);
    const char* Aj = (const char*)(g_ln + ((size_t)b * SEQ + j * 128) * DIM);

    auto LOAD_AI = [&]() {
#pragma unroll
        for (int u = 0; u < 32; ++u) {
            const int idx = tid + u * 256;
            const int r = idx >> 6, c16 = idx & 63;
            CP_ASYNC16(sb + OFF_AI + r * 1024 + (((uint32_t)(c16 ^ (r & 7))) << 4),
                       Ai + (size_t)r * 1024 + c16 * 16);
        }
    };
    auto LOAD_QJ = [&](int q, int bufoff) {
#pragma unroll
        for (int u = 0; u < 8; ++u) {
            const int idx = tid + u * 256;
            const int r = idx >> 4, c16 = idx & 15;
            CP_ASYNC16(sb + bufoff + r * 256 + (((uint32_t)(c16 ^ (r & 7))) << 4),
                       Aj + (size_t)r * 1024 + q * 256 + c16 * 16);
        }
    };

    if (!diag) LOAD_QJ(0, OFF_J0);
    CP_COMMIT();                               // G0: Aj q0
    LOAD_AI();
    CP_COMMIT();                               // G1: Ai
    if (!diag) LOAD_QJ(1, OFF_J1);
    CP_COMMIT();                               // G2: Aj q1
    CP_WAITN(1);                               // G0,G1 done
    __syncthreads();

    const int mgrp = wid >> 1, ngrp = wid & 1;
    const int laneAr = lane & 15, chA = lane >> 4;
    const int rB = (lane & 7) + ((lane >> 4) << 3);
    const int chB = (lane >> 3) & 1;

    float acc[2][8][4] = {};

    // one K-quarter (8 k16 steps); A always from resident Ai
    auto COMPUTE_Q = [&](int q, uint32_t bBase, uint32_t bStride, uint32_t bC16off) {
#pragma unroll 4
        for (int kk = 0; kk < 8; ++kk) {
            uint32_t a[2][4];
#pragma unroll
            for (int mb = 0; mb < 2; ++mb) {
                const int rowA = mgrp * 32 + mb * 16 + laneAr;
                const uint32_t c16 = q * 16 + 2 * kk + chA;
                LDSM_X4(a[mb][0], a[mb][1], a[mb][2], a[mb][3],
                        sb + OFF_AI + rowA * 1024 + (((uint32_t)(c16 ^ (rowA & 7))) << 4));
            }
#pragma unroll
            for (int nb16 = 0; nb16 < 4; ++nb16) {
                const int rowB = ngrp * 64 + nb16 * 16 + rB;
                const uint32_t c16b = bC16off + 2 * kk + chB;
                uint32_t b0, b1, b2, b3;
                LDSM_X4T(b0, b1, b2, b3,
                         bBase + rowB * bStride + (((uint32_t)(c16b ^ (rowB & 7))) << 4));
#pragma unroll
                for (int mb = 0; mb < 2; ++mb) {
                    MMA16816(acc[mb][nb16 * 2 + 0], a[mb][0], a[mb][1], a[mb][2], a[mb][3], b0, b1);
                    MMA16816(acc[mb][nb16 * 2 + 1], a[mb][0], a[mb][1], a[mb][2], a[mb][3], b2, b3);
                }
            }
        }
    };
    auto BQ = [&](int q) -> uint32_t {
        return diag ? (sb + OFF_AI) : (sb + ((q & 1) ? OFF_J1 : OFF_J0));
    };
    const uint32_t bStride = diag ? 1024u : 256u;

    // q0
    COMPUTE_Q(0, BQ(0), bStride, diag ? 0 : 0);
    __syncthreads();
    if (!diag) LOAD_QJ(2, OFF_J0);
    CP_COMMIT();                               // G3: Aj q2
    CP_WAITN(1);                               // G2 done
    __syncthreads();
    // q1
    COMPUTE_Q(1, BQ(1), bStride, diag ? 16 : 0);
    __syncthreads();
    if (!diag) LOAD_QJ(3, OFF_J1);
    CP_COMMIT();                               // G4: Aj q3
    CP_WAITN(1);                               // G3 done
    __syncthreads();
    // q2
    COMPUTE_Q(2, BQ(2), bStride, diag ? 32 : 0);
    __syncthreads();
    CP_WAITN(0);                               // G4 done
    __syncthreads();
    // q3
    COMPUTE_Q(3, BQ(3), bStride, diag ? 48 : 0);

    // ---- epilogue: e = exp(10v - 10); row sums (block i) + col sums (block j)
    float rE[2][2] = {}, rV[2][2] = {}, cE[8][2] = {}, cV[8][2] = {};
#pragma unroll
    for (int mb = 0; mb < 2; ++mb)
#pragma unroll
        for (int nbi = 0; nbi < 8; ++nbi)
#pragma unroll
            for (int jj = 0; jj < 4; ++jj) {
                const float v = acc[mb][nbi][jj];
                float t = fmaf(v, L2E10, -L2E10);
                float e;
                asm("ex2.approx.ftz.f32 %0, %1;" : "=f"(e) : "f"(t));
                const int lr = mgrp * 32 + mb * 16 + (lane >> 2) + ((jj & 2) ? 8 : 0);
                const int lc = ngrp * 64 + nbi * 8 + 2 * (lane & 3) + (jj & 1);
                if (!(diag && lr == lc)) {
                    rE[mb][jj >> 1] += e; rV[mb][jj >> 1] += v;
                    cE[nbi][jj & 1] += e; cV[nbi][jj & 1] += v;
                }
            }

    float* rowEs = reinterpret_cast<float*>(smem + OFF_RED);          // [2][128]
    float* rowVs = rowEs + 256;
    float* colEs = rowEs + 512;                                       // [4][128]
    float* colVs = rowEs + 1024;

#pragma unroll
    for (int mb = 0; mb < 2; ++mb)
#pragma unroll
        for (int h = 0; h < 2; ++h) {
            float e = rE[mb][h], vv = rV[mb][h];
            e += __shfl_xor_sync(0xFFFFFFFFu, e, 1);
            e += __shfl_xor_sync(0xFFFFFFFFu, e, 2);
            vv += __shfl_xor_sync(0xFFFFFFFFu, vv, 1);
            vv += __shfl_xor_sync(0xFFFFFFFFu, vv, 2);
            if ((lane & 3) == 0) {
                const int lr = mgrp * 32 + mb * 16 + (lane >> 2) + h * 8;
                rowEs[ngrp * 128 + lr] = e;
                rowVs[ngrp * 128 + lr] = vv;
            }
        }
#pragma unroll
    for (int nbi = 0; nbi < 8; ++nbi)
#pragma unroll
        for (int cp = 0; cp < 2; ++cp) {
            float e = cE[nbi][cp], vv = cV[nbi][cp];
            e += __shfl_xor_sync(0xFFFFFFFFu, e, 4);
            e += __shfl_xor_sync(0xFFFFFFFFu, e, 8);
            e += __shfl_xor_sync(0xFFFFFFFFu, e, 16);
            vv += __shfl_xor_sync(0xFFFFFFFFu, vv, 4);
            vv += __shfl_xor_sync(0xFFFFFFFFu, vv, 8);
            vv += __shfl_xor_sync(0xFFFFFFFFu, vv, 16);
            if (lane < 4) {
                const int lc = ngrp * 64 + nbi * 8 + 2 * lane + cp;
                colEs[mgrp * 128 + lc] = e;
                colVs[mgrp * 128 + lc] = vv;
            }
        }
    __syncthreads();

    if (tid < 128) {
        const int sl = ((b * NBLK + i) * NBLK + j) * 128;
        g_es[sl + tid] = rowEs[tid] + rowEs[128 + tid];
        g_vs[sl + tid] = rowVs[tid] + rowVs[128 + tid];
    } else if (!diag) {
        const int c = tid - 128;
        const int sl = ((b * NBLK + j) * NBLK + i) * 128;
        g_es[sl + c] = colEs[c] + colEs[128 + c] + colEs[256 + c] + colEs[384 + c];
        g_vs[sl + c] = colVs[c] + colVs[128 + c] + colVs[256 + c] + colVs[384 + c];
    }
}

// ---------------- kernel 3: combine + full reduce (last-block finish) -----
__global__ void __launch_bounds__(128) disp_reduce(float* out) {
    const int tid = threadIdx.x;
    const int row = blockIdx.x * 128 + tid;
    const int b = row >> 11, r = row & 2047;
    const int iblk = r >> 7, lr = r & 127;
    const int base = ((b * NBLK + iblk) * NBLK) * 128 + lr;
    float es = 0.f, vs = 0.f;
#pragma unroll
    for (int jb = 0; jb < NBLK; ++jb) { es += g_es[base + jb * 128]; vs += g_vs[base + jb * 128]; }
    float acc = 2047.0f * (logf(es) + 10.0f) - 10.0f * vs;
#pragma unroll
    for (int o = 16; o; o >>= 1) acc += __shfl_xor_sync(0xFFFFFFFFu, acc, o);
    __shared__ float s[4];
    __shared__ bool isLast;
    if ((tid & 31) == 0) s[tid >> 5] = acc;
    __syncthreads();
    if (tid == 0) {
        g_partial[blockIdx.x] = s[0] + s[1] + s[2] + s[3];
        __threadfence();
        isLast = (atomicAdd(&g_done, 1u) == 127u);
    }
    __syncthreads();
    if (isLast) {
        float v = g_partial[tid];
#pragma unroll
        for (int o = 16; o; o >>= 1) v += __shfl_xor_sync(0xFFFFFFFFu, v, o);
        if ((tid & 31) == 0) s[tid >> 5] = v;
        __syncthreads();
        if (tid == 0) {
            out[0] = 0.5f * (s[0] + s[1] + s[2] + s[3]) / 33554432.0f;  // B*S*S
            g_done = 0;   // reset for next graph replay
        }
    }
}

extern "C" void kernel_launch(void* const* d_in, const int* in_sizes, int n_in,
                              void* d_out, int out_size) {
    (void)in_sizes; (void)n_in; (void)out_size;
    cudaFuncSetAttribute(disp_main, cudaFuncAttributeMaxDynamicSharedMemorySize, SMEM_TOTAL);
    const float* x = (const float*)d_in[0];
    disp_norm<<<BATCH * SEQ / 8, 256>>>(x);
    disp_main<<<BATCH * NPAIR, 256, SMEM_TOTAL>>>();
    disp_reduce<<<128, 128>>>((float*)d_out);
}

// round 8
// speedup vs baseline: 1.0887x; 1.0887x over previous
#include <cuda_runtime.h>
#include <cuda_bf16.h>
#include <cstdint>

// DispersiveLoss: loss = 0.5 * mean_{b,s,t!=s}[ LSE_s - sim_st ], sim = cos/0.1
// Per row: (S-1)*(log(sum_{t!=s} e^{sim-10}) + 10) - 10*sum_{t!=s} cos
// Symmetric-pair formulation (i<=j). sm_103: mma.sync bf16 + ldmatrix + cp.async.

namespace {
constexpr int BATCH = 8, SEQ = 2048, DIM = 512;
constexpr int NBLK = 16;
constexpr int NPAIR = NBLK * (NBLK + 1) / 2;   // 136
constexpr float L2E10 = 14.4269504088896341f;  // 10*log2(e)
// SMEM: 3 half-K buffers (128 rows x 256 bf16 = 64KB each) + reduction area
constexpr int OFF_B0  = 0;
constexpr int OFF_B1  = 65536;
constexpr int OFF_B2  = 131072;
constexpr int OFF_RED = 196608;            // 1536 floats
constexpr int SMEM_TOTAL = OFF_RED + 6144; // 202752
}

__device__ __nv_bfloat16 g_ln[(size_t)BATCH * SEQ * DIM];
__device__ float g_es[BATCH * NBLK * NBLK * 128];
__device__ float g_vs[BATCH * NBLK * NBLK * 128];
__device__ float g_partial[128];
__device__ unsigned int g_done;

__device__ __forceinline__ uint32_t smem_u32(const void* p) {
    uint32_t a;
    asm("{ .reg .u64 t; cvta.to.shared.u64 t, %1; cvt.u32.u64 %0, t; }" : "=r"(a) : "l"(p));
    return a;
}
#define CP_ASYNC16(sa, ga) \
    asm volatile("cp.async.cg.shared.global [%0], [%1], 16;" :: "r"(sa), "l"(ga))
#define CP_COMMIT() asm volatile("cp.async.commit_group;")
#define CP_WAITN(n) asm volatile("cp.async.wait_group %0;" :: "n"(n))
#define LDSM_X4(r0, r1, r2, r3, addr) \
    asm volatile("ldmatrix.sync.aligned.m8n8.x4.shared.b16 {%0,%1,%2,%3}, [%4];" \
                 : "=r"(r0), "=r"(r1), "=r"(r2), "=r"(r3) : "r"(addr))
#define LDSM_X4T(r0, r1, r2, r3, addr) \
    asm volatile("ldmatrix.sync.aligned.m8n8.x4.trans.shared.b16 {%0,%1,%2,%3}, [%4];" \
                 : "=r"(r0), "=r"(r1), "=r"(r2), "=r"(r3) : "r"(addr))
#define MMA16816(c, A0, A1, A2, A3, B0, B1) \
    asm volatile("mma.sync.aligned.m16n8k16.row.col.f32.bf16.bf16.f32 " \
                 "{%0,%1,%2,%3}, {%4,%5,%6,%7}, {%8,%9}, {%0,%1,%2,%3};" \
                 : "+f"((c)[0]), "+f"((c)[1]), "+f"((c)[2]), "+f"((c)[3]) \
                 : "r"(A0), "r"(A1), "r"(A2), "r"(A3), "r"(B0), "r"(B1))

// ------- kernel 1: L2-normalize rows -> bf16 (2 rows per warp, ILP) -------
__global__ void __launch_bounds__(256) disp_norm(const float* __restrict__ x) {
    const int wid = threadIdx.x >> 5, lane = threadIdx.x & 31;
    const int row0 = (blockIdx.x * 8 + wid) * 2;
    const float4* s0 = reinterpret_cast<const float4*>(x + (size_t)row0 * DIM);
    const float4* s1 = reinterpret_cast<const float4*>(x + (size_t)(row0 + 1) * DIM);
    float4 a[4], c[4];
#pragma unroll
    for (int k = 0; k < 4; ++k) { a[k] = s0[lane + 32 * k]; c[k] = s1[lane + 32 * k]; }
    float ss0 = 0.f, ss1 = 0.f;
#pragma unroll
    for (int k = 0; k < 4; ++k) {
        ss0 += a[k].x * a[k].x + a[k].y * a[k].y + a[k].z * a[k].z + a[k].w * a[k].w;
        ss1 += c[k].x * c[k].x + c[k].y * c[k].y + c[k].z * c[k].z + c[k].w * c[k].w;
    }
#pragma unroll
    for (int o = 16; o; o >>= 1) {
        ss0 += __shfl_xor_sync(0xFFFFFFFFu, ss0, o);
        ss1 += __shfl_xor_sync(0xFFFFFFFFu, ss1, o);
    }
    const float i0 = 1.0f / fmaxf(sqrtf(ss0), 1e-8f);
    const float i1 = 1.0f / fmaxf(sqrtf(ss1), 1e-8f);
    __nv_bfloat162* d0 = reinterpret_cast<__nv_bfloat162*>(g_ln + (size_t)row0 * DIM);
    __nv_bfloat162* d1 = reinterpret_cast<__nv_bfloat162*>(g_ln + (size_t)(row0 + 1) * DIM);
#pragma unroll
    for (int k = 0; k < 4; ++k) {
        d0[(lane + 32 * k) * 2 + 0] = __floats2bfloat162_rn(a[k].x * i0, a[k].y * i0);
        d0[(lane + 32 * k) * 2 + 1] = __floats2bfloat162_rn(a[k].z * i0, a[k].w * i0);
        d1[(lane + 32 * k) * 2 + 0] = __floats2bfloat162_rn(c[k].x * i1, c[k].y * i1);
        d1[(lane + 32 * k) * 2 + 1] = __floats2bfloat162_rn(c[k].z * i1, c[k].w * i1);
    }
}

// ---------------- kernel 2: symmetric tile-pair GEMM + exp-sums ----------
// 1088 CTAs = 8 batches x 136 pairs (i<=j). 256 threads = 8 warps (4M x 2N),
// warp tile 32x64 over the 128x128 product A_i * A_j^T. K=512 in two halves.
__global__ void __launch_bounds__(256, 1) disp_main() {
    extern __shared__ char smem[];
    const uint32_t sb = smem_u32(smem);
    const int tid = threadIdx.x, wid = tid >> 5, lane = tid & 31;
    const int bx = blockIdx.x;
    const int b = bx / NPAIR;
    int p = bx - b * NPAIR;
    int i = 0;
    while (p >= NBLK - i) { p -= NBLK - i; ++i; }
    const int j = i + p;
    const bool diag = (i == j);

    const char* Ai = (const char*)(g_ln + ((size_t)b * SEQ + i * 128) * DIM);
    const char* Aj = (const char*)(g_ln + ((size_t)b * SEQ + j * 128) * DIM);

    auto LOAD_HALF = [&](const char* src, int kh, int bufoff) {
#pragma unroll
        for (int u = 0; u < 16; ++u) {
            const int idx = tid + u * 256;
            const int r = idx >> 5, c16 = idx & 31;
            const uint32_t sa = sb + bufoff + r * 512 + (((uint32_t)(c16 ^ (r & 7))) << 4);
            CP_ASYNC16(sa, src + (size_t)r * 1024 + kh * 512 + c16 * 16);
        }
    };

    LOAD_HALF(Ai, 0, OFF_B0);
    if (!diag) LOAD_HALF(Aj, 0, OFF_B1);
    CP_COMMIT();
    LOAD_HALF(Ai, 1, OFF_B2);
    CP_COMMIT();
    CP_WAITN(1);
    __syncthreads();

    const int mgrp = wid >> 1, ngrp = wid & 1;
    const int laneAr = lane & 15, chA = lane >> 4;
    const int rB = (lane & 7) + ((lane >> 4) << 3);
    const int chB = (lane >> 3) & 1;

    float acc[2][8][4] = {};

    auto COMPUTE_HALF = [&](uint32_t aBase, uint32_t bBase) {
#pragma unroll 4
        for (int kk = 0; kk < 16; ++kk) {
            uint32_t a[2][4];
#pragma unroll
            for (int mb = 0; mb < 2; ++mb) {
                const int rowA = mgrp * 32 + mb * 16 + laneAr;
                const uint32_t c16 = 2 * kk + chA;
                LDSM_X4(a[mb][0], a[mb][1], a[mb][2], a[mb][3],
                        aBase + rowA * 512 + (((uint32_t)(c16 ^ (rowA & 7))) << 4));
            }
#pragma unroll
            for (int nb16 = 0; nb16 < 4; ++nb16) {
                const int rowB = ngrp * 64 + nb16 * 16 + rB;
                const uint32_t c16b = 2 * kk + chB;
                uint32_t b0, b1, b2, b3;
                LDSM_X4T(b0, b1, b2, b3,
                         bBase + rowB * 512 + (((uint32_t)(c16b ^ (rowB & 7))) << 4));
#pragma unroll
                for (int mb = 0; mb < 2; ++mb) {
                    MMA16816(acc[mb][nb16 * 2 + 0], a[mb][0], a[mb][1], a[mb][2], a[mb][3], b0, b1);
                    MMA16816(acc[mb][nb16 * 2 + 1], a[mb][0], a[mb][1], a[mb][2], a[mb][3], b2, b3);
                }
            }
        }
    };

    COMPUTE_HALF(sb + OFF_B0, sb + (diag ? OFF_B0 : OFF_B1));
    __syncthreads();
    if (!diag) { LOAD_HALF(Aj, 1, OFF_B1); CP_COMMIT(); }
    CP_WAITN(0);
    __syncthreads();
    COMPUTE_HALF(sb + OFF_B2, sb + (diag ? OFF_B2 : OFF_B1));

    // ---- epilogue: e = exp(10v - 10); row sums (block i) + col sums (block j)
    float rE[2][2] = {}, rV[2][2] = {}, cE[8][2] = {}, cV[8][2] = {};
#pragma unroll
    for (int mb = 0; mb < 2; ++mb)
#pragma unroll
        for (int nbi = 0; nbi < 8; ++nbi)
#pragma unroll
            for (int jj = 0; jj < 4; ++jj) {
                const float v = acc[mb][nbi][jj];
                float t = fmaf(v, L2E10, -L2E10);
                float e;
                asm("ex2.approx.ftz.f32 %0, %1;" : "=f"(e) : "f"(t));
                const int lr = mgrp * 32 + mb * 16 + (lane >> 2) + ((jj & 2) ? 8 : 0);
                const int lc = ngrp * 64 + nbi * 8 + 2 * (lane & 3) + (jj & 1);
                if (!(diag && lr == lc)) {
                    rE[mb][jj >> 1] += e; rV[mb][jj >> 1] += v;
                    cE[nbi][jj & 1] += e; cV[nbi][jj & 1] += v;
                }
            }

    float* rowEs = reinterpret_cast<float*>(smem + OFF_RED);          // [2][128]
    float* rowVs = rowEs + 256;
    float* colEs = rowEs + 512;                                       // [4][128]
    float* colVs = rowEs + 1024;

#pragma unroll
    for (int mb = 0; mb < 2; ++mb)
#pragma unroll
        for (int h = 0; h < 2; ++h) {
            float e = rE[mb][h], vv = rV[mb][h];
            e += __shfl_xor_sync(0xFFFFFFFFu, e, 1);
            e += __shfl_xor_sync(0xFFFFFFFFu, e, 2);
            vv += __shfl_xor_sync(0xFFFFFFFFu, vv, 1);
            vv += __shfl_xor_sync(0xFFFFFFFFu, vv, 2);
            if ((lane & 3) == 0) {
                const int lr = mgrp * 32 + mb * 16 + (lane >> 2) + h * 8;
                rowEs[ngrp * 128 + lr] = e;
                rowVs[ngrp * 128 + lr] = vv;
            }
        }
#pragma unroll
    for (int nbi = 0; nbi < 8; ++nbi)
#pragma unroll
        for (int cp = 0; cp < 2; ++cp) {
            float e = cE[nbi][cp], vv = cV[nbi][cp];
            e += __shfl_xor_sync(0xFFFFFFFFu, e, 4);
            e += __shfl_xor_sync(0xFFFFFFFFu, e, 8);
            e += __shfl_xor_sync(0xFFFFFFFFu, e, 16);
            vv += __shfl_xor_sync(0xFFFFFFFFu, vv, 4);
            vv += __shfl_xor_sync(0xFFFFFFFFu, vv, 8);
            vv += __shfl_xor_sync(0xFFFFFFFFu, vv, 16);
            if (lane < 4) {
                const int lc = ngrp * 64 + nbi * 8 + 2 * lane + cp;
                colEs[mgrp * 128 + lc] = e;
                colVs[mgrp * 128 + lc] = vv;
            }
        }
    __syncthreads();

    if (tid < 128) {
        const int sl = ((b * NBLK + i) * NBLK + j) * 128;
        g_es[sl + tid] = rowEs[tid] + rowEs[128 + tid];
        g_vs[sl + tid] = rowVs[tid] + rowVs[128 + tid];
    } else if (!diag) {
        const int c = tid - 128;
        const int sl = ((b * NBLK + j) * NBLK + i) * 128;
        g_es[sl + c] = colEs[c] + colEs[128 + c] + colEs[256 + c] + colEs[384 + c];
        g_vs[sl + c] = colVs[c] + colVs[128 + c] + colVs[256 + c] + colVs[384 + c];
    }
}

// ---------------- kernel 3: combine + full reduce (last-block finish) -----
__global__ void __launch_bounds__(128) disp_reduce(float* out) {
    const int tid = threadIdx.x;
    const int row = blockIdx.x * 128 + tid;
    const int b = row >> 11, r = row & 2047;
    const int iblk = r >> 7, lr = r & 127;
    const int base = ((b * NBLK + iblk) * NBLK) * 128 + lr;
    float es = 0.f, vs = 0.f;
#pragma unroll
    for (int jb = 0; jb < NBLK; ++jb) { es += g_es[base + jb * 128]; vs += g_vs[base + jb * 128]; }
    float acc = 2047.0f * (logf(es) + 10.0f) - 10.0f * vs;
#pragma unroll
    for (int o = 16; o; o >>= 1) acc += __shfl_xor_sync(0xFFFFFFFFu, acc, o);
    __shared__ float s[4];
    __shared__ bool isLast;
    if ((tid & 31) == 0) s[tid >> 5] = acc;
    __syncthreads();
    if (tid == 0) {
        g_partial[blockIdx.x] = s[0] + s[1] + s[2] + s[3];
        __threadfence();
        isLast = (atomicAdd(&g_done, 1u) == 127u);
    }
    __syncthreads();
    if (isLast) {
        float v = g_partial[tid];
#pragma unroll
        for (int o = 16; o; o >>= 1) v += __shfl_xor_sync(0xFFFFFFFFu, v, o);
        if ((tid & 31) == 0) s[tid >> 5] = v;
        __syncthreads();
        if (tid == 0) {
            out[0] = 0.5f * (s[0] + s[1] + s[2] + s[3]) / 33554432.0f;  // B*S*S
            g_done = 0;   // reset for next graph replay
        }
    }
}

extern "C" void kernel_launch(void* const* d_in, const int* in_sizes, int n_in,
                              void* d_out, int out_size) {
    (void)in_sizes; (void)n_in; (void)out_size;
    cudaFuncSetAttribute(disp_main, cudaFuncAttributeMaxDynamicSharedMemorySize, SMEM_TOTAL);
    const float* x = (const float*)d_in[0];
    disp_norm<<<BATCH * SEQ / 16, 256>>>(x);
    disp_main<<<BATCH * NPAIR, 256, SMEM_TOTAL>>>();
    disp_reduce<<<128, 128>>>((float*)d_out);
}